// round 10
// baseline (speedup 1.0000x reference)
#include <cuda_runtime.h>
#include <cstdint>

typedef unsigned long long ull;

__constant__ float cCC[6]  = {0.f, 0.2f, 0.3f, 0.8f, (float)(8.0/9.0), 1.0f};
__constant__ float cBWv[6] = {(float)(35.0/384.0), 0.f, (float)(500.0/1113.0),
                              (float)(125.0/192.0), (float)(-2187.0/6784.0),
                              (float)(11.0/84.0)};

// ---- smem layout (float offsets) ----
#define oXs  0        /* [g:2][smp:2][128] = 512 */
#define oA   512      /* [g:2][smp:2][128] = 512 */
#define oH1  1024     /* [ks:4][smp:2][128] = 1024  (G1 partials) */
#define oH2  2048     /* 1024 (G2 partials) */
#define oPb  3072     /* [g:2][p:2][rank:4][256] = 4096 */
#define oStg 7168     /* [g:2][p:2][256] = 1024 */
#define oScr 8192     /* 32 */
#define oTx  8224     /* 4 */
#define oDx  8228     /* 4 */
#define oLp  8232     /* 4 */
#define SMF  8236

__device__ __forceinline__ ull pk(float w) {
  ull r; asm("mov.b64 %0, {%1, %2};" : "=l"(r) : "f"(w), "f"(w)); return r;
}
__device__ __forceinline__ ull mk2(float a, float b) {
  ull r; asm("mov.b64 %0, {%1, %2};" : "=l"(r) : "f"(a), "f"(b)); return r;
}
__device__ __forceinline__ float lo32(ull v) { return __uint_as_float((unsigned)v); }
__device__ __forceinline__ float hi32(ull v) { return __uint_as_float((unsigned)(v >> 32)); }
__device__ __forceinline__ ull f2fma(ull a, ull b, ull c) {
  ull d; asm("fma.rn.f32x2 %0,%1,%2,%3;" : "=l"(d) : "l"(a), "l"(b), "l"(c)); return d;
}
__device__ __forceinline__ ull f2add(ull a, ull b) {
  ull d; asm("add.rn.f32x2 %0,%1,%2;" : "=l"(d) : "l"(a), "l"(b)); return d;
}
__device__ __forceinline__ ull f2mul(ull a, ull b) {
  ull d; asm("mul.rn.f32x2 %0,%1,%2;" : "=l"(d) : "l"(a), "l"(b)); return d;
}
__device__ __forceinline__ float wsum(float v) {
#pragma unroll
  for (int o = 16; o > 0; o >>= 1) v += __shfl_xor_sync(0xffffffffu, v, o);
  return v;
}
__device__ __forceinline__ uint32_t smem_u32(const void* p) {
  uint32_t a;
  asm("{.reg .u64 t; cvta.to.shared.u64 t, %1; cvt.u32.u64 %0, t;}" : "=r"(a) : "l"(p));
  return a;
}
__device__ __forceinline__ uint32_t mapa_u32(uint32_t addr, uint32_t rank) {
  uint32_t ra; asm("mapa.shared::cluster.u32 %0, %1, %2;" : "=r"(ra) : "r"(addr), "r"(rank));
  return ra;
}
__device__ __forceinline__ float ldcf(uint32_t addr, uint32_t rank) {
  uint32_t ra = mapa_u32(addr, rank);
  float v; asm volatile("ld.shared::cluster.f32 %0, [%1];" : "=f"(v) : "r"(ra)); return v;
}
__device__ __forceinline__ void csync() {
  asm volatile("barrier.cluster.arrive.aligned;" ::: "memory");
  asm volatile("barrier.cluster.wait.aligned;" ::: "memory");
}
__device__ __forceinline__ void mbar_init(uint32_t mb, unsigned cnt) {
  asm volatile("mbarrier.init.shared::cta.b64 [%0], %1;" :: "r"(mb), "r"(cnt) : "memory");
}
__device__ __forceinline__ void mbar_arm(uint32_t mb, unsigned tx) {
  asm volatile("mbarrier.arrive.expect_tx.shared::cta.b64 _, [%0], %1;"
               :: "r"(mb), "r"(tx) : "memory");
}
__device__ __forceinline__ void bulk_copy256(uint32_t dst_cluster, uint32_t src_cta,
                                             uint32_t rmb_cluster) {
  asm volatile(
      "cp.async.bulk.shared::cluster.shared::cta.mbarrier::complete_tx::bytes "
      "[%0], [%1], 256, [%2];"
      :: "r"(dst_cluster), "r"(src_cta), "r"(rmb_cluster) : "memory");
}
__device__ __forceinline__ void waitp(uint32_t mb, unsigned ph) {
  unsigned done;
  asm volatile(
      "{\n\t.reg .pred p;\n\t"
      "mbarrier.try_wait.parity.acquire.cluster.shared::cta.b64 p, [%1], %2;\n\t"
      "selp.u32 %0,1,0,p;\n\t}"
      : "=r"(done) : "r"(mb), "r"(ph) : "memory");
  while (!done) {
    asm volatile(
        "{\n\t.reg .pred p;\n\t"
        "mbarrier.try_wait.parity.acquire.cluster.shared::cta.b64 p, [%1], %2, 0x989680;\n\t"
        "selp.u32 %0,1,0,p;\n\t}"
        : "=r"(done) : "r"(mb), "r"(ph) : "memory");
  }
}
__device__ __forceinline__ float ftanh(float x) {
  float e = __expf(2.f * x);
  return 1.f - __fdividef(2.f, e + 1.f);
}

// Engine GEMM: 128 threads (tau = cg + 32*ks), 2 samples, 128 out cols, K=128.
// Thread computes cols {4cg..4cg+3} over k in [32ks, 32ks+32).
// src: [smp:2][128]; dst: [ks:4][smp:2][128].
__device__ __forceinline__ void gemm_e(const ull (&w)[4][16],
                                       const float* __restrict__ src,
                                       float* __restrict__ dst, int ks, int cg) {
  const float* sp = src + (ks << 5);
  float* dp = dst + (ks << 8) + (cg << 2);
#pragma unroll
  for (int s = 0; s < 2; ++s) {
    ull a0 = 0, a1 = 0, a2 = 0, a3 = 0;
#pragma unroll
    for (int i = 0; i < 8; ++i) {
      ulonglong2 x = *(const ulonglong2*)(sp + s * 128 + (i << 2));
      a0 = f2fma(w[0][2 * i], x.x, a0); a0 = f2fma(w[0][2 * i + 1], x.y, a0);
      a1 = f2fma(w[1][2 * i], x.x, a1); a1 = f2fma(w[1][2 * i + 1], x.y, a1);
      a2 = f2fma(w[2][2 * i], x.x, a2); a2 = f2fma(w[2][2 * i + 1], x.y, a2);
      a3 = f2fma(w[3][2 * i], x.x, a3); a3 = f2fma(w[3][2 * i + 1], x.y, a3);
    }
    float4 r;
    r.x = lo32(a0) + hi32(a0);
    r.y = lo32(a1) + hi32(a1);
    r.z = lo32(a2) + hi32(a2);
    r.w = lo32(a3) + hi32(a3);
    *(float4*)(dp + s * 128) = r;
  }
}

// RK advance (registers); stage 5 updates y.
__device__ __forceinline__ void rk_adv(int st, ull kacc, float dt,
    ull& k0, ull& k1, ull& k2, ull& k3, ull& k4, ull& y, ull& xs) {
  ull acc;
  switch (st) {
    case 0:
      k0 = kacc; acc = f2mul(pk(0.2f), k0);
      xs = f2fma(pk(dt), acc, y); break;
    case 1:
      k1 = kacc;
      acc = f2mul(pk(0.075f), k0);
      acc = f2fma(pk(0.225f), k1, acc);
      xs = f2fma(pk(dt), acc, y); break;
    case 2:
      k2 = kacc;
      acc = f2mul(pk((float)(44.0 / 45.0)), k0);
      acc = f2fma(pk((float)(-56.0 / 15.0)), k1, acc);
      acc = f2fma(pk((float)(32.0 / 9.0)), k2, acc);
      xs = f2fma(pk(dt), acc, y); break;
    case 3:
      k3 = kacc;
      acc = f2mul(pk((float)(19372.0 / 6561.0)), k0);
      acc = f2fma(pk((float)(-25360.0 / 2187.0)), k1, acc);
      acc = f2fma(pk((float)(64448.0 / 6561.0)), k2, acc);
      acc = f2fma(pk((float)(-212.0 / 729.0)), k3, acc);
      xs = f2fma(pk(dt), acc, y); break;
    case 4:
      k4 = kacc;
      acc = f2mul(pk((float)(9017.0 / 3168.0)), k0);
      acc = f2fma(pk((float)(-355.0 / 33.0)), k1, acc);
      acc = f2fma(pk((float)(46732.0 / 5247.0)), k2, acc);
      acc = f2fma(pk((float)(49.0 / 176.0)), k3, acc);
      acc = f2fma(pk((float)(-5103.0 / 18656.0)), k4, acc);
      xs = f2fma(pk(dt), acc, y); break;
    default:
      acc = f2mul(pk((float)(35.0 / 384.0)), k0);
      acc = f2fma(pk((float)(500.0 / 1113.0)), k2, acc);
      acc = f2fma(pk((float)(125.0 / 192.0)), k3, acc);
      acc = f2fma(pk((float)(-2187.0 / 6784.0)), k4, acc);
      acc = f2fma(pk((float)(11.0 / 84.0)), kacc, acc);
      y = f2fma(pk(dt), acc, y);
      xs = y; break;
  }
}

// fold G2 partials -> push to 4 ranks -> wait -> assemble -> RK (eng1 only)
#define EXCH(G, P, PSTG, PCOEF, PARV, Y, XS, K0, K1, K2, K3, K4, DOT) do {      \
  float v0 = 0.f, v1 = 0.f;                                                     \
  _Pragma("unroll")                                                             \
  for (int q = 0; q < 4; ++q) {                                                 \
    v0 += sm[oH2 + (q << 8) + tau];                                             \
    v1 += sm[oH2 + (q << 8) + 128 + tau];                                       \
  }                                                                             \
  ((ull*)(sm + oStg))[(((G) << 1) + (P)) * 128 + tau] = mk2(v0, v1);            \
  __syncwarp();                                                                 \
  if (lane == 0) {                                                              \
    asm volatile("fence.proxy.async.shared::cta;" ::: "memory");                \
    const uint32_t so = stgb + ((uint32_t)(((G) << 1) + (P)) << 10) +           \
                        ((uint32_t)wi << 8);                                    \
    const uint32_t dof = ((uint32_t)(G) << 13) + ((uint32_t)(P) << 12);         \
    const uint32_t mof = (uint32_t)(((G) << 1) + (P)) << 3;                     \
    bulk_copy256(dstb[0] + dof, so, rmbb[0] + mof);                             \
    bulk_copy256(dstb[1] + dof, so, rmbb[1] + mof);                             \
    bulk_copy256(dstb[2] + dof, so, rmbb[2] + mof);                             \
    bulk_copy256(dstb[3] + dof, so, rmbb[3] + mof);                             \
  }                                                                             \
  {                                                                             \
    const uint32_t lmb = mb0 + ((uint32_t)(((G) << 1) + (P)) << 3);             \
    waitp(lmb, PARV); (PARV) ^= 1;                                              \
    if (t == 128) mbar_arm(lmb, 4096u);                                         \
  }                                                                             \
  {                                                                             \
    const float* pb = sm + oPb + ((((G) << 1) + (P)) << 10);                    \
    ull kacc = f2add(                                                           \
        f2add(*(const ull*)(pb + 2 * tau), *(const ull*)(pb + 256 + 2 * tau)),  \
        f2add(*(const ull*)(pb + 512 + 2 * tau), *(const ull*)(pb + 768 + 2 * tau))); \
    kacc = f2add(kacc, b2p);                                                    \
    DOT = f2fma(f2mul(XS, kacc), pk(PCOEF), DOT);                               \
    rk_adv(PSTG, kacc, dt, K0, K1, K2, K3, K4, Y, XS);                          \
    sm[oXs + (G) * 256 + tau] = lo32(XS);                                       \
    sm[oXs + (G) * 256 + 128 + tau] = hi32(XS);                                 \
  }                                                                             \
} while (0)

#define TANH(G, TCUR, COEF, TR) do {                                            \
  const float bias = fmaf(TCUR, u1r, b1r);                                      \
  float h0 = bias, h1 = bias;                                                   \
  _Pragma("unroll")                                                             \
  for (int q = 0; q < 4; ++q) {                                                 \
    h0 += sm[oH1 + (q << 8) + tau];                                             \
    h1 += sm[oH1 + (q << 8) + 128 + tau];                                       \
  }                                                                             \
  const float a0 = ftanh(h0), a1 = ftanh(h1);                                   \
  sm[oA + (G) * 256 + tau] = a0;                                                \
  sm[oA + (G) * 256 + 128 + tau] = a1;                                          \
  TR = f2fma(mk2((1.f - a0 * a0) * mr, (1.f - a1 * a1) * mr), pk(COEF), TR);    \
} while (0)

__global__ void __launch_bounds__(256, 1) __cluster_dims__(4, 1, 1)
vino_kernel(const float* __restrict__ x0g, const float* __restrict__ W1g,
            const float* __restrict__ b1g, const float* __restrict__ u1g,
            const float* __restrict__ W2g, const float* __restrict__ b2g,
            const int* __restrict__ nsp, float* __restrict__ out, int B) {
  __shared__ __align__(16) float sm[SMF];
  __shared__ __align__(8) unsigned long long smbar[4];   // [g][p]
  const int t = threadIdx.x;
  const int lane = t & 31;
  const int tau = t & 127;
  const int cg = tau & 31, ks = tau >> 5;
  const bool e1 = (t >= 128);          // eng1 = G2/exchange/RK engine
  const int wi = (t >> 5) & 3;         // warp index within engine
  uint32_t rank; asm("mov.u32 %0, %%cluster_ctarank;" : "=r"(rank));
  const int hbase = (int)rank << 7;
  const int sb = (blockIdx.x >> 2) << 2;

  // ---- engine weight tile: 4 cols x 16 k-pairs = 128 regs ----
  ull wp[4][16];
  if (!e1) {
    // W1 slice: h-cols hbase+4cg+j, k (d) = 32ks + 2i
#pragma unroll
    for (int j = 0; j < 4; ++j)
#pragma unroll
      for (int i = 0; i < 16; ++i) {
        const int k0 = (ks << 5) + 2 * i;
        const int col = hbase + 4 * cg + j;
        wp[j][i] = mk2(W1g[k0 * 512 + col], W1g[(k0 + 1) * 512 + col]);
      }
  } else {
    // W2 slice: out-cols 4cg+j, k (h) = hbase + 32ks + 2i
#pragma unroll
    for (int j = 0; j < 4; ++j)
#pragma unroll
      for (int i = 0; i < 16; ++i) {
        const int r0 = hbase + (ks << 5) + 2 * i;
        const int col = 4 * cg + j;
        wp[j][i] = mk2(W2g[r0 * 128 + col], W2g[(r0 + 1) * 128 + col]);
      }
  }

  // ---- per-role constants/state ----
  float b1r = 0.f, u1r = 0.f, mr = 0.f;
  ull b2p = 0;
  ull yA = 0, yB = 0, xsA = 0, xsB = 0;
  if (!e1) {
    b1r = b1g[hbase + tau];
    u1r = u1g[hbase + tau];
#pragma unroll 4
    for (int i = 0; i < 128; ++i)
      mr = fmaf(W1g[i * 512 + hbase + tau], W2g[(hbase + tau) * 128 + i], mr);
  } else {
    b2p = pk(b2g[tau]);
    yA = mk2(x0g[(sb + 0) * 128 + tau], x0g[(sb + 1) * 128 + tau]);
    yB = mk2(x0g[(sb + 2) * 128 + tau], x0g[(sb + 3) * 128 + tau]);
    xsA = yA; xsB = yB;
    sm[oXs + tau] = lo32(xsA);        sm[oXs + 128 + tau] = hi32(xsA);
    sm[oXs + 256 + tau] = lo32(xsB);  sm[oXs + 384 + tau] = hi32(xsB);
  }

  // ---- mbarriers + bulk-copy addresses ----
  const uint32_t mb0 = smem_u32(&smbar[0]);
  if (t == 0) {
#pragma unroll
    for (int m = 0; m < 4; ++m) { mbar_init(mb0 + m * 8, 1); mbar_arm(mb0 + m * 8, 4096u); }
  }
  const uint32_t stgb = smem_u32(sm + oStg);
  uint32_t dstb[4], rmbb[4];
  {
    const uint32_t doff = smem_u32(sm + oPb) + ((uint32_t)rank << 10) + ((uint32_t)wi << 8);
#pragma unroll
    for (uint32_t r = 0; r < 4; ++r) {
      dstb[r] = mapa_u32(doff, r);
      rmbb[r] = mapa_u32(mb0, r);
    }
  }

  // ---- log p(x0) ----
  if (e1) {
    float s0 = wsum(lo32(yA) * lo32(yA)), s1 = wsum(hi32(yA) * hi32(yA));
    float s2 = wsum(lo32(yB) * lo32(yB)), s3 = wsum(hi32(yB) * hi32(yB));
    if (lane == 0) {
      sm[oScr + wi * 4 + 0] = s0; sm[oScr + wi * 4 + 1] = s1;
      sm[oScr + wi * 4 + 2] = s2; sm[oScr + wi * 4 + 3] = s3;
    }
  }
  __syncthreads();
  if (t < 4) {
    const int g = t >> 1, sp2 = t & 1;
    float ss = 0.f;
#pragma unroll
    for (int q = 0; q < 4; ++q) ss += sm[oScr + q * 4 + g * 2 + sp2];
    sm[oLp + t] = -0.5f * ss - 117.6241322501981f;  // 64*log(2*pi)
  }
  csync();  // mbar arming + smem init visible cluster-wide

  const int ns = *nsp;
  const int nper = 6 * ns;
  const float dt = 1.0f / (float)ns;
  ull kA0 = 0, kA1 = 0, kA2 = 0, kA3 = 0, kA4 = 0;
  ull kB0 = 0, kB1 = 0, kB2 = 0, kB3 = 0, kB4 = 0;
  ull trA = 0, trB = 0, dotA = 0, dotB = 0;
  unsigned parA0 = 0, parA1 = 0, parB0 = 0, parB1 = 0;
  int stg = 0; float tst = 0.f;

#pragma unroll 1
  for (int i = 0; i < nper; ++i) {
    const float coef = dt * cBWv[stg];
    const float tcur = tst + cCC[stg] * dt;
    const int pA = i & 1;

    // ---- s1: G1(A,i) || G2(B,i-1) ----
    if (!e1) gemm_e(wp, sm + oXs, sm + oH1, ks, cg);
    else if (i > 0) gemm_e(wp, sm + oA + 256, sm + oH2, ks, cg);
    __syncthreads();

    // ---- s2: tanh(A) || exch(B,i-1) ----
    if (!e1) { TANH(0, tcur, coef, trA); }
    else if (i > 0) {
      const int ps = (stg == 0) ? 5 : stg - 1;
      const int pB = (i - 1) & 1;
      const float pco = dt * cBWv[ps];
      if (pB) EXCH(1, 1, ps, pco, parB1, yB, xsB, kB0, kB1, kB2, kB3, kB4, dotB);
      else    EXCH(1, 0, ps, pco, parB0, yB, xsB, kB0, kB1, kB2, kB3, kB4, dotB);
    }
    __syncthreads();

    // ---- s3: G1(B,i) || G2(A,i) ----
    if (!e1) gemm_e(wp, sm + oXs + 256, sm + oH1, ks, cg);
    else gemm_e(wp, sm + oA, sm + oH2, ks, cg);
    __syncthreads();

    // ---- s4: tanh(B) || exch(A,i) ----
    if (!e1) { TANH(1, tcur, coef, trB); }
    else {
      if (pA) EXCH(0, 1, stg, coef, parA1, yA, xsA, kA0, kA1, kA2, kA3, kA4, dotA);
      else    EXCH(0, 0, stg, coef, parA0, yA, xsA, kA0, kA1, kA2, kA3, kA4, dotA);
    }
    __syncthreads();

    if (++stg == 6) { stg = 0; tst += dt; }
  }

  // ---- tail: G2(B, last) + exch(B, last) ----
  if (e1) gemm_e(wp, sm + oA + 256, sm + oH2, ks, cg);
  __syncthreads();
  if (e1) {
    const int pB = (nper - 1) & 1;
    const float pco = dt * cBWv[5];
    if (pB) EXCH(1, 1, 5, pco, parB1, yB, xsB, kB0, kB1, kB2, kB3, kB4, dotB);
    else    EXCH(1, 0, 5, pco, parB0, yB, xsB, kB0, kB1, kB2, kB3, kB4, dotB);
  }
  __syncthreads();

  // ---- outputs: z (eng1 owns y) ----
  if (e1) {
    out[(sb + 0) * 128 + tau] = lo32(yA);
    out[(sb + 1) * 128 + tau] = hi32(yA);
    out[(sb + 2) * 128 + tau] = lo32(yB);
    out[(sb + 3) * 128 + tau] = hi32(yB);
  }

  // ---- final reductions ----
  if (!e1) {
    float a = wsum(lo32(trA)), b = wsum(hi32(trA));
    float c2 = wsum(lo32(trB)), d = wsum(hi32(trB));
    if (lane == 0) {
      sm[oScr + wi * 4 + 0] = a;  sm[oScr + wi * 4 + 1] = b;
      sm[oScr + wi * 4 + 2] = c2; sm[oScr + wi * 4 + 3] = d;
    }
  } else {
    float a = wsum(lo32(dotA)), b = wsum(hi32(dotA));
    float c2 = wsum(lo32(dotB)), d = wsum(hi32(dotB));
    if (lane == 0) {
      sm[oScr + 16 + wi * 4 + 0] = a;  sm[oScr + 16 + wi * 4 + 1] = b;
      sm[oScr + 16 + wi * 4 + 2] = c2; sm[oScr + 16 + wi * 4 + 3] = d;
    }
  }
  __syncthreads();
  if (t < 4) {
    const int g = t >> 1, sp2 = t & 1;
    float T = 0.f, D = 0.f;
#pragma unroll
    for (int q = 0; q < 4; ++q) {
      T += sm[oScr + q * 4 + g * 2 + sp2];
      D += sm[oScr + 16 + q * 4 + g * 2 + sp2];
    }
    sm[oTx + t] = T;
    sm[oDx + t] = D;
  }
  csync();
  if (t < 4) {
    const uint32_t ta = smem_u32(&sm[oTx + t]);
    float T4 = 0.f;
#pragma unroll
    for (uint32_t r = 0; r < 4; ++r) T4 += ldcf(ta, r);
    out[B * 128 + sb + t]     = sm[oLp + t] - T4;   // log_px
    out[B * 128 + B + sb + t] = sm[oDx + t] - T4;   // kl
  }
  csync();  // keep smem alive until peers finish remote reads
}

extern "C" void kernel_launch(void* const* d_in, const int* in_sizes, int n_in,
                              void* d_out, int out_size) {
  const float* x0 = (const float*)d_in[0];
  const float* W1 = (const float*)d_in[1];
  const float* b1 = (const float*)d_in[2];
  const float* u1 = (const float*)d_in[3];
  const float* W2 = (const float*)d_in[4];
  const float* b2 = (const float*)d_in[5];
  const int*   ns = (const int*)d_in[6];
  float* out = (float*)d_out;
  int B = in_sizes[0] / 128;
  vino_kernel<<<B, 256>>>(x0, W1, b1, u1, W2, b2, ns, out, B);
}